// round 15
// baseline (speedup 1.0000x reference)
#include <cuda_runtime.h>
#include <cuda_fp16.h>
#include <cuda_bf16.h>
#include <math.h>

#define NN 100000
#define EE 1600000
#define NEG_SLOPE 0.2f
#define SCAN_B 512
#define NBLK ((NN + SCAN_B - 1) / SCAN_B)      // 196
#define TC_BLOCKS ((NN + 127) / 128)            // 782 (tensor-core GEMM blocks)
#define HIST_BLOCKS ((EE / 4 + 255) / 256)      // 1563
#define FULL 0xFFFFFFFFu

// ---------------- scratch (device globals) ----------------
__device__ float g_h1[NN * 64];     // layer1 GEMM output [N,H*D]
__device__ float g_as1[NN * 8];
__device__ float g_ad1[NN * 8];
__device__ float g_out1[NN * 64];   // layer1 final (ELU'd)
__device__ float g_g2[NN * 16];     // layer2 GEMM output
__device__ float g_as2[NN];
__device__ float g_ad2[NN];
__device__ int   g_deg[NN];         // zero at load; self-reset each call
__device__ int   g_off[NN + 1];     // CSR offsets, sentinel off[NN]=EE
__device__ unsigned short g_rank16[EE];  // per-edge rank within its dst segment
__device__ int   g_csr[EE];         // src node ids, grouped by dst
__device__ int   g_bsum[NBLK];
__device__ int   g_bar1, g_bar2, g_done;   // software grid barriers (self-reset)

__device__ __forceinline__ unsigned su32(const void* p) {
    return (unsigned)__cvta_generic_to_shared(p);
}

// ---------------- KA: tensor-core GEMM1 (+logits) fused with degree histogram ----------------
__global__ void __launch_bounds__(256) kA_gemm1_hist(
    const float* __restrict__ x, const float* __restrict__ W1,
    const float* __restrict__ a1s, const float* __restrict__ a1d,
    const int* __restrict__ dst)
{
    if (blockIdx.x >= TC_BLOCKS) {
        // ---- histogram part: 4 edges/thread, record ranks (uint16) ----
        int t = (blockIdx.x - TC_BLOCKS) * 256 + threadIdx.x;
        if (t >= EE / 4) return;
        int4 d4 = ((const int4*)dst)[t];
        int r0 = atomicAdd(&g_deg[d4.x], 1);
        int r1 = atomicAdd(&g_deg[d4.y], 1);
        int r2 = atomicAdd(&g_deg[d4.z], 1);
        int r3 = atomicAdd(&g_deg[d4.w], 1);
        ((ushort4*)g_rank16)[t] = make_ushort4((unsigned short)r0, (unsigned short)r1,
                                               (unsigned short)r2, (unsigned short)r3);
        return;
    }

    // ---- GEMM part: 128 rows/block, 8 warps, mma.sync m16n8k16 fp16->fp32 ----
    __shared__ __half xs[128 * 72];
    __shared__ __half ws[64 * 72];
    __shared__ float sA[128];

    int tid = threadIdx.x;
    int wid = tid >> 5, lane = tid & 31;
    int rowBase = blockIdx.x * 128;
    if (tid < 128) sA[tid] = (tid < 64) ? a1s[tid] : a1d[tid - 64];

    float acc[8][4];
#pragma unroll
    for (int nt = 0; nt < 8; nt++)
#pragma unroll
        for (int c = 0; c < 4; c++) acc[nt][c] = 0.0f;

#pragma unroll 1
    for (int stage = 0; stage < 2; stage++) {
        if (stage) __syncthreads();

#pragma unroll
        for (int i = 0; i < 8; i++) {
            int idx4 = tid + i * 256;
            int r = idx4 >> 4;
            int k4 = (idx4 & 15) * 4;
            int grow = rowBase + r;
            float4 v = make_float4(0.f, 0.f, 0.f, 0.f);
            if (grow < NN)
                v = __ldg((const float4*)(x + (size_t)grow * 128 + stage * 64 + k4));
            *(__half2*)(&xs[r * 72 + k4])     = __floats2half2_rn(v.x, v.y);
            *(__half2*)(&xs[r * 72 + k4 + 2]) = __floats2half2_rn(v.z, v.w);
        }
#pragma unroll
        for (int i = 0; i < 4; i++) {
            int idx4 = tid + i * 256;
            int r = idx4 >> 4;
            int k4 = (idx4 & 15) * 4;
            float4 v = __ldg((const float4*)(W1 + (size_t)(stage * 64 + r) * 64 + k4));
            *(__half2*)(&ws[r * 72 + k4])     = __floats2half2_rn(v.x, v.y);
            *(__half2*)(&ws[r * 72 + k4 + 2]) = __floats2half2_rn(v.z, v.w);
        }
        __syncthreads();

#pragma unroll
        for (int kcl = 0; kcl < 4; kcl++) {
            unsigned a0, a1, a2, a3;
            unsigned aaddr = su32(xs) +
                ((wid * 16 + (lane & 15)) * 72 + kcl * 16 + (lane >> 4) * 8) * 2;
            asm volatile(
                "ldmatrix.sync.aligned.m8n8.x4.shared.b16 {%0,%1,%2,%3}, [%4];"
                : "=r"(a0), "=r"(a1), "=r"(a2), "=r"(a3) : "r"(aaddr));
#pragma unroll
            for (int nt = 0; nt < 8; nt++) {
                unsigned b0, b1;
                unsigned baddr = su32(ws) +
                    ((kcl * 16 + (lane & 15)) * 72 + nt * 8) * 2;
                asm volatile(
                    "ldmatrix.sync.aligned.m8n8.x2.trans.shared.b16 {%0,%1}, [%2];"
                    : "=r"(b0), "=r"(b1) : "r"(baddr));
                asm volatile(
                    "mma.sync.aligned.m16n8k16.row.col.f32.f16.f16.f32 "
                    "{%0,%1,%2,%3}, {%4,%5,%6,%7}, {%8,%9}, {%0,%1,%2,%3};"
                    : "+f"(acc[nt][0]), "+f"(acc[nt][1]),
                      "+f"(acc[nt][2]), "+f"(acc[nt][3])
                    : "r"(a0), "r"(a1), "r"(a2), "r"(a3), "r"(b0), "r"(b1));
            }
        }
    }

    // ---- epilogue: store h1 + per-head logits ----
    int q = lane & 3;
    int r0 = rowBase + wid * 16 + (lane >> 2);
    int r1 = r0 + 8;

#pragma unroll
    for (int nt = 0; nt < 8; nt++) {
        int col = nt * 8 + 2 * q;
        if (r0 < NN)
            *(float2*)(g_h1 + (size_t)r0 * 64 + col) = make_float2(acc[nt][0], acc[nt][1]);
        if (r1 < NN)
            *(float2*)(g_h1 + (size_t)r1 * 64 + col) = make_float2(acc[nt][2], acc[nt][3]);
    }

#pragma unroll
    for (int h = 0; h < 8; h++) {
        float as0 = sA[h * 8 + 2 * q], as1v = sA[h * 8 + 2 * q + 1];
        float ad0 = sA[64 + h * 8 + 2 * q], ad1v = sA[64 + h * 8 + 2 * q + 1];
        float s0 = acc[h][0] * as0 + acc[h][1] * as1v;
        float d0 = acc[h][0] * ad0 + acc[h][1] * ad1v;
        float s1 = acc[h][2] * as0 + acc[h][3] * as1v;
        float d1 = acc[h][2] * ad0 + acc[h][3] * ad1v;
#pragma unroll
        for (int o = 1; o <= 2; o <<= 1) {
            s0 += __shfl_xor_sync(FULL, s0, o);
            d0 += __shfl_xor_sync(FULL, d0, o);
            s1 += __shfl_xor_sync(FULL, s1, o);
            d1 += __shfl_xor_sync(FULL, d1, o);
        }
        if (q == 0) {
            if (r0 < NN) { g_as1[r0 * 8 + h] = s0; g_ad1[r0 * 8 + h] = d0; }
            if (r1 < NN) { g_as1[r1 * 8 + h] = s1; g_ad1[r1 * 8 + h] = d1; }
        }
    }
}

// ---------------- fused CSR: scan -> barrier -> apply -> barrier -> scatter ----------------
__global__ void __launch_bounds__(512) k_csr(const int* __restrict__ src,
                                             const int* __restrict__ dst) {
    __shared__ int sd[SCAN_B];
    int tid = threadIdx.x;
    int b = blockIdx.x;
    int i = b * SCAN_B + tid;

    // phase 1: block-local exclusive scan of g_deg
    int v = (i < NN) ? g_deg[i] : 0;
    sd[tid] = v;
    __syncthreads();
    for (int ofs = 1; ofs < SCAN_B; ofs <<= 1) {
        int t = (tid >= ofs) ? sd[tid - ofs] : 0;
        __syncthreads();
        sd[tid] += t;
        __syncthreads();
    }
    if (i < NN) g_off[i] = sd[tid] - v;
    if (tid == SCAN_B - 1) g_bsum[b] = sd[tid];

    // grid barrier 1 (all NBLK blocks co-resident: 196 blocks << capacity)
    __threadfence();
    __syncthreads();
    if (tid == 0) {
        atomicAdd(&g_bar1, 1);
        volatile int* vb = &g_bar1;
        while (*vb < NBLK) { }
    }
    __syncthreads();
    __threadfence();

    // phase 2: cross-block base + apply + sentinel + deg reset
    __shared__ int sbase;
    if (tid < 32) {
        int p = 0;
        for (int k = tid; k < b; k += 32) p += g_bsum[k];
#pragma unroll
        for (int o = 16; o; o >>= 1) p += __shfl_xor_sync(FULL, p, o);
        if (tid == 0) sbase = p;
    }
    __syncthreads();
    if (i < NN) {
        int o = g_off[i] + sbase;
        g_off[i] = o;
        if (i == NN - 1) g_off[NN] = o + v;
        g_deg[i] = 0;
    }

    // grid barrier 2
    __threadfence();
    __syncthreads();
    if (tid == 0) {
        atomicAdd(&g_bar2, 1);
        volatile int* vb = &g_bar2;
        while (*vb < NBLK) { }
    }
    __syncthreads();
    __threadfence();

    // phase 3: atomic-free scatter, grid-stride (4 edges/thread/iter)
    for (int t = b * SCAN_B + tid; t < EE / 4; t += NBLK * SCAN_B) {
        int4 s4 = ((const int4*)src)[t];
        int4 d4 = ((const int4*)dst)[t];
        ushort4 r4 = ((const ushort4*)g_rank16)[t];
        g_csr[g_off[d4.x] + r4.x] = s4.x;
        g_csr[g_off[d4.y] + r4.y] = s4.y;
        g_csr[g_off[d4.z] + r4.z] = s4.z;
        g_csr[g_off[d4.w] + r4.w] = s4.w;
    }

    // reset barrier counters for next graph replay (last block only)
    __syncthreads();
    if (tid == 0) {
        __threadfence();
        if (atomicAdd(&g_done, 1) == NBLK - 1) {
            g_bar1 = 0;
            g_bar2 = 0;
            g_done = 0;
            __threadfence();
        }
    }
}

// ---------------- G1: warp-per-dst gather, 8 edges in flight ----------------
__global__ void __launch_bounds__(256) g1_gather(const float* __restrict__ b1) {
    int warp = (blockIdx.x * 256 + threadIdx.x) >> 5;
    int lane = threadIdx.x & 31;
    if (warp >= NN) return;
    int n = warp;
    int off = g_off[n];
    int deg = g_off[n + 1] - off;
    int h8 = lane & 7;
    int h4 = lane >> 2;
    float adf = g_ad1[n * 8 + h8];

    float2 acc = make_float2(0.0f, 0.0f);
    float den = 0.0f;

    int sreg = (lane < deg) ? g_csr[off + lane] : 0;

    for (int base = 0; base < deg; base += 32) {
        int sreg_n = 0;
        if (base + 32 < deg) {
            int nl = base + 32 + lane;
            sreg_n = (nl < deg) ? g_csr[off + nl] : 0;
        }
        int cnt = min(32, deg - base);

        int sl0 = __shfl_sync(FULL, sreg, lane >> 3);
        float as = g_as1[sl0 * 8 + h8];

        for (int g = 0; g < cnt; g += 8) {
            bool hasB = (g + 4 < cnt);
            float asB = 0.0f;
            if (hasB) {
                int slB = __shfl_sync(FULL, sreg, g + 4 + (lane >> 3));
                asB = g_as1[slB * 8 + h8];
            }
            float as_nx = 0.0f;
            if (g + 8 < cnt) {
                int slN = __shfl_sync(FULL, sreg, g + 8 + (lane >> 3));
                as_nx = g_as1[slN * 8 + h8];
            }

            float eA = as + adf;
            eA = (eA >= 0.0f) ? eA : NEG_SLOPE * eA;
            float pA = __expf(eA);
            if (base + g + (lane >> 3) >= deg) pA = 0.0f;

            float pB = 0.0f;
            if (hasB) {
                float eB = asB + adf;
                eB = (eB >= 0.0f) ? eB : NEG_SLOPE * eB;
                pB = __expf(eB);
                if (base + g + 4 + (lane >> 3) >= deg) pB = 0.0f;
            }

            float2 v[8];
            float pj[8];
#pragma unroll
            for (int j = 0; j < 4; j++) {
                int s = __shfl_sync(FULL, sreg, g + j);
                pj[j] = __shfl_sync(FULL, pA, j * 8 + h4);
                v[j] = *(const float2*)(g_h1 + (size_t)s * 64 + 2 * lane);
            }
#pragma unroll
            for (int j = 0; j < 4; j++) {
                int s = __shfl_sync(FULL, sreg, g + 4 + j);
                pj[4 + j] = __shfl_sync(FULL, pB, j * 8 + h4);
                v[4 + j] = *(const float2*)(g_h1 + (size_t)s * 64 + 2 * lane);
            }
#pragma unroll
            for (int j = 0; j < 8; j++) {
                acc.x += pj[j] * v[j].x;
                acc.y += pj[j] * v[j].y;
                den += pj[j];
            }
            as = as_nx;
        }
        sreg = sreg_n;
    }

    float inv = (den > 0.0f) ? (1.0f / den) : 0.0f;
    float r0 = acc.x * inv + b1[2 * lane];
    float r1 = acc.y * inv + b1[2 * lane + 1];
    r0 = (r0 > 0.0f) ? r0 : (__expf(r0) - 1.0f);
    r1 = (r1 > 0.0f) ? r1 : (__expf(r1) - 1.0f);
    *(float2*)(g_out1 + (size_t)n * 64 + 2 * lane) = make_float2(r0, r1);
}

// ---------------- K5: tensor-core GEMM2 (+layer2 attention logits) ----------------
__global__ void __launch_bounds__(256) k5_gemm2(
    const float* __restrict__ W2, const float* __restrict__ a2s,
    const float* __restrict__ a2d)
{
    __shared__ __half xs[128 * 72];
    __shared__ __half ws[64 * 24];
    __shared__ float sA[32];

    int tid = threadIdx.x;
    int wid = tid >> 5, lane = tid & 31;
    int rowBase = blockIdx.x * 128;
    if (tid < 32) sA[tid] = (tid < 16) ? a2s[tid] : a2d[tid - 16];

#pragma unroll
    for (int i = 0; i < 8; i++) {
        int idx4 = tid + i * 256;
        int r = idx4 >> 4;
        int k4 = (idx4 & 15) * 4;
        int grow = rowBase + r;
        float4 v = make_float4(0.f, 0.f, 0.f, 0.f);
        if (grow < NN)
            v = *(const float4*)(g_out1 + (size_t)grow * 64 + k4);
        *(__half2*)(&xs[r * 72 + k4])     = __floats2half2_rn(v.x, v.y);
        *(__half2*)(&xs[r * 72 + k4 + 2]) = __floats2half2_rn(v.z, v.w);
    }
    if (tid < 256) {
        int r = tid >> 2;
        int k4 = (tid & 3) * 4;
        float4 v = __ldg((const float4*)(W2 + (size_t)r * 16 + k4));
        *(__half2*)(&ws[r * 24 + k4])     = __floats2half2_rn(v.x, v.y);
        *(__half2*)(&ws[r * 24 + k4 + 2]) = __floats2half2_rn(v.z, v.w);
    }
    __syncthreads();

    float acc[2][4];
#pragma unroll
    for (int nt = 0; nt < 2; nt++)
#pragma unroll
        for (int c = 0; c < 4; c++) acc[nt][c] = 0.0f;

#pragma unroll
    for (int kcl = 0; kcl < 4; kcl++) {
        unsigned a0, a1, a2, a3;
        unsigned aaddr = su32(xs) +
            ((wid * 16 + (lane & 15)) * 72 + kcl * 16 + (lane >> 4) * 8) * 2;
        asm volatile(
            "ldmatrix.sync.aligned.m8n8.x4.shared.b16 {%0,%1,%2,%3}, [%4];"
            : "=r"(a0), "=r"(a1), "=r"(a2), "=r"(a3) : "r"(aaddr));
#pragma unroll
        for (int nt = 0; nt < 2; nt++) {
            unsigned b0, b1;
            unsigned baddr = su32(ws) +
                ((kcl * 16 + (lane & 15)) * 24 + nt * 8) * 2;
            asm volatile(
                "ldmatrix.sync.aligned.m8n8.x2.trans.shared.b16 {%0,%1}, [%2];"
                : "=r"(b0), "=r"(b1) : "r"(baddr));
            asm volatile(
                "mma.sync.aligned.m16n8k16.row.col.f32.f16.f16.f32 "
                "{%0,%1,%2,%3}, {%4,%5,%6,%7}, {%8,%9}, {%0,%1,%2,%3};"
                : "+f"(acc[nt][0]), "+f"(acc[nt][1]),
                  "+f"(acc[nt][2]), "+f"(acc[nt][3])
                : "r"(a0), "r"(a1), "r"(a2), "r"(a3), "r"(b0), "r"(b1));
        }
    }

    int q = lane & 3;
    int r0 = rowBase + wid * 16 + (lane >> 2);
    int r1 = r0 + 8;

#pragma unroll
    for (int nt = 0; nt < 2; nt++) {
        int col = nt * 8 + 2 * q;
        if (r0 < NN)
            *(float2*)(g_g2 + (size_t)r0 * 16 + col) = make_float2(acc[nt][0], acc[nt][1]);
        if (r1 < NN)
            *(float2*)(g_g2 + (size_t)r1 * 16 + col) = make_float2(acc[nt][2], acc[nt][3]);
    }

    float s0 = 0.0f, d0 = 0.0f, s1 = 0.0f, d1 = 0.0f;
#pragma unroll
    for (int nt = 0; nt < 2; nt++) {
        int c0 = nt * 8 + 2 * q, c1 = c0 + 1;
        s0 += acc[nt][0] * sA[c0] + acc[nt][1] * sA[c1];
        d0 += acc[nt][0] * sA[16 + c0] + acc[nt][1] * sA[16 + c1];
        s1 += acc[nt][2] * sA[c0] + acc[nt][3] * sA[c1];
        d1 += acc[nt][2] * sA[16 + c0] + acc[nt][3] * sA[16 + c1];
    }
#pragma unroll
    for (int o = 1; o <= 2; o <<= 1) {
        s0 += __shfl_xor_sync(FULL, s0, o);
        d0 += __shfl_xor_sync(FULL, d0, o);
        s1 += __shfl_xor_sync(FULL, s1, o);
        d1 += __shfl_xor_sync(FULL, d1, o);
    }
    if (q == 0) {
        if (r0 < NN) { g_as2[r0] = s0; g_ad2[r0] = d0; }
        if (r1 < NN) { g_as2[r1] = s1; g_ad2[r1] = d1; }
    }
}

// ---------------- G2: warp-per-dst gather, 4 edges in flight ----------------
__global__ void __launch_bounds__(256) g2_gather(const float* __restrict__ b2,
                                                 float* __restrict__ out) {
    int warp = (blockIdx.x * 256 + threadIdx.x) >> 5;
    int lane = threadIdx.x & 31;
    if (warp >= NN) return;
    int n = warp;
    int off = g_off[n];
    int deg = g_off[n + 1] - off;
    int half = lane >> 4;
    int d16 = lane & 15;
    float ad = g_ad2[n];

    float acc = 0.0f, den = 0.0f;

    int sreg = (lane < deg) ? g_csr[off + lane] : 0;
    float as = g_as2[sreg];

    for (int base = 0; base < deg; base += 32) {
        int sreg_n = 0;
        float as_n = 0.0f;
        if (base + 32 < deg) {
            int nl = base + 32 + lane;
            sreg_n = (nl < deg) ? g_csr[off + nl] : 0;
            as_n = g_as2[sreg_n];
        }

        float e = as + ad;
        e = (e >= 0.0f) ? e : NEG_SLOPE * e;
        float p = __expf(e);
        if (base + lane >= deg) p = 0.0f;
        int cnt = min(32, deg - base);

        int g = 0;
        for (; g + 4 <= cnt; g += 4) {
            int sa = __shfl_sync(FULL, sreg, g + half);
            float pa = __shfl_sync(FULL, p, g + half);
            int sb = __shfl_sync(FULL, sreg, g + 2 + half);
            float pb = __shfl_sync(FULL, p, g + 2 + half);
            float va = g_g2[(size_t)sa * 16 + d16];
            float vb = g_g2[(size_t)sb * 16 + d16];
            acc += pa * va;
            den += pa;
            acc += pb * vb;
            den += pb;
        }
        for (; g < cnt; g += 2) {
            int s = __shfl_sync(FULL, sreg, g + half);
            float pj = __shfl_sync(FULL, p, g + half);
            float v = g_g2[(size_t)s * 16 + d16];
            acc += pj * v;
            den += pj;
        }
        sreg = sreg_n;
        as = as_n;
    }

    acc += __shfl_xor_sync(FULL, acc, 16);
    den += __shfl_xor_sync(FULL, den, 16);

    float z = ((den > 0.0f) ? (acc / den) : 0.0f) + b2[d16];

    float m = z;
#pragma unroll
    for (int ofs = 1; ofs < 16; ofs <<= 1)
        m = fmaxf(m, __shfl_xor_sync(FULL, m, ofs));
    float sum = __expf(z - m);
#pragma unroll
    for (int ofs = 1; ofs < 16; ofs <<= 1)
        sum += __shfl_xor_sync(FULL, sum, ofs);
    float lse = m + logf(sum);

    if (lane < 16) out[(size_t)n * 16 + d16] = z - lse;
}

// ---------------- launcher ----------------
extern "C" void kernel_launch(void* const* d_in, const int* in_sizes, int n_in,
                              void* d_out, int out_size) {
    const float* x   = (const float*)d_in[0];
    const int*   ei  = (const int*)d_in[1];
    const float* W1  = (const float*)d_in[2];
    const float* a1s = (const float*)d_in[3];
    const float* a1d = (const float*)d_in[4];
    const float* b1  = (const float*)d_in[5];
    const float* W2  = (const float*)d_in[6];
    const float* a2s = (const float*)d_in[7];
    const float* a2d = (const float*)d_in[8];
    const float* b2  = (const float*)d_in[9];
    float* out = (float*)d_out;

    const int* src = ei;
    const int* dst = ei + EE;

    const int TB = 256;
    kA_gemm1_hist<<<TC_BLOCKS + HIST_BLOCKS, TB>>>(x, W1, a1s, a1d, dst);
    k_csr<<<NBLK, SCAN_B>>>(src, dst);          // fused scan+apply+scatter
    g1_gather<<<(NN * 32 + TB - 1) / TB, TB>>>(b1);
    k5_gemm2<<<TC_BLOCKS, TB>>>(W2, a2s, a2d);
    g2_gather<<<(NN * 32 + TB - 1) / TB, TB>>>(b2, out);
}

// round 16
// speedup vs baseline: 1.0600x; 1.0600x over previous
#include <cuda_runtime.h>
#include <cuda_fp16.h>
#include <cuda_bf16.h>
#include <math.h>

#define NN 100000
#define EE 1600000
#define NEG_SLOPE 0.2f
#define SCAN_B 512
#define NBLK ((NN + SCAN_B - 1) / SCAN_B)      // 196
#define TC_BLOCKS ((NN + 127) / 128)            // 782 (tensor-core GEMM blocks)
#define HIST_BLOCKS ((EE / 4 + 255) / 256)      // 1563
#define FULL 0xFFFFFFFFu

// ---------------- scratch (device globals) ----------------
__device__ float  g_h1[NN * 64];     // layer1 GEMM output [N,H*D]
__device__ float  g_as1[NN * 8];
__device__ float  g_ad1[NN * 8];
__device__ __half g_out1h[NN * 64];  // layer1 final (ELU'd), fp16 (feeds fp16 GEMM2)
__device__ float  g_g2[NN * 16];     // layer2 GEMM output
__device__ float  g_as2[NN];
__device__ float  g_ad2[NN];
__device__ int    g_deg[NN];         // zero at load; self-reset by s3 each call
__device__ int    g_off[NN + 1];     // CSR offsets, sentinel off[NN]=EE
__device__ unsigned short g_rank16[EE];  // per-edge rank within its dst segment
__device__ int    g_csr[EE];         // src node ids, grouped by dst
__device__ int    g_bsum[NBLK];

__device__ __forceinline__ unsigned su32(const void* p) {
    return (unsigned)__cvta_generic_to_shared(p);
}

// ---------------- KA: tensor-core GEMM1 (+logits) fused with degree histogram ----------------
__global__ void __launch_bounds__(256) kA_gemm1_hist(
    const float* __restrict__ x, const float* __restrict__ W1,
    const float* __restrict__ a1s, const float* __restrict__ a1d,
    const int* __restrict__ dst)
{
    if (blockIdx.x >= TC_BLOCKS) {
        // ---- histogram part: 4 edges/thread, record ranks (uint16) ----
        int t = (blockIdx.x - TC_BLOCKS) * 256 + threadIdx.x;
        if (t >= EE / 4) return;
        int4 d4 = ((const int4*)dst)[t];
        int r0 = atomicAdd(&g_deg[d4.x], 1);
        int r1 = atomicAdd(&g_deg[d4.y], 1);
        int r2 = atomicAdd(&g_deg[d4.z], 1);
        int r3 = atomicAdd(&g_deg[d4.w], 1);
        ((ushort4*)g_rank16)[t] = make_ushort4((unsigned short)r0, (unsigned short)r1,
                                               (unsigned short)r2, (unsigned short)r3);
        return;
    }

    // ---- GEMM part: 128 rows/block, 8 warps, mma.sync m16n8k16 fp16->fp32 ----
    __shared__ __half xs[128 * 72];
    __shared__ __half ws[64 * 72];
    __shared__ float sA[128];

    int tid = threadIdx.x;
    int wid = tid >> 5, lane = tid & 31;
    int rowBase = blockIdx.x * 128;
    if (tid < 128) sA[tid] = (tid < 64) ? a1s[tid] : a1d[tid - 64];

    float acc[8][4];
#pragma unroll
    for (int nt = 0; nt < 8; nt++)
#pragma unroll
        for (int c = 0; c < 4; c++) acc[nt][c] = 0.0f;

#pragma unroll 1
    for (int stage = 0; stage < 2; stage++) {
        if (stage) __syncthreads();

#pragma unroll
        for (int i = 0; i < 8; i++) {
            int idx4 = tid + i * 256;
            int r = idx4 >> 4;
            int k4 = (idx4 & 15) * 4;
            int grow = rowBase + r;
            float4 v = make_float4(0.f, 0.f, 0.f, 0.f);
            if (grow < NN)
                v = __ldg((const float4*)(x + (size_t)grow * 128 + stage * 64 + k4));
            *(__half2*)(&xs[r * 72 + k4])     = __floats2half2_rn(v.x, v.y);
            *(__half2*)(&xs[r * 72 + k4 + 2]) = __floats2half2_rn(v.z, v.w);
        }
#pragma unroll
        for (int i = 0; i < 4; i++) {
            int idx4 = tid + i * 256;
            int r = idx4 >> 4;
            int k4 = (idx4 & 15) * 4;
            float4 v = __ldg((const float4*)(W1 + (size_t)(stage * 64 + r) * 64 + k4));
            *(__half2*)(&ws[r * 72 + k4])     = __floats2half2_rn(v.x, v.y);
            *(__half2*)(&ws[r * 72 + k4 + 2]) = __floats2half2_rn(v.z, v.w);
        }
        __syncthreads();

#pragma unroll
        for (int kcl = 0; kcl < 4; kcl++) {
            unsigned a0, a1, a2, a3;
            unsigned aaddr = su32(xs) +
                ((wid * 16 + (lane & 15)) * 72 + kcl * 16 + (lane >> 4) * 8) * 2;
            asm volatile(
                "ldmatrix.sync.aligned.m8n8.x4.shared.b16 {%0,%1,%2,%3}, [%4];"
                : "=r"(a0), "=r"(a1), "=r"(a2), "=r"(a3) : "r"(aaddr));
#pragma unroll
            for (int nt = 0; nt < 8; nt++) {
                unsigned b0, b1;
                unsigned baddr = su32(ws) +
                    ((kcl * 16 + (lane & 15)) * 72 + nt * 8) * 2;
                asm volatile(
                    "ldmatrix.sync.aligned.m8n8.x2.trans.shared.b16 {%0,%1}, [%2];"
                    : "=r"(b0), "=r"(b1) : "r"(baddr));
                asm volatile(
                    "mma.sync.aligned.m16n8k16.row.col.f32.f16.f16.f32 "
                    "{%0,%1,%2,%3}, {%4,%5,%6,%7}, {%8,%9}, {%0,%1,%2,%3};"
                    : "+f"(acc[nt][0]), "+f"(acc[nt][1]),
                      "+f"(acc[nt][2]), "+f"(acc[nt][3])
                    : "r"(a0), "r"(a1), "r"(a2), "r"(a3), "r"(b0), "r"(b1));
            }
        }
    }

    // ---- epilogue: store h1 + per-head logits ----
    int q = lane & 3;
    int r0 = rowBase + wid * 16 + (lane >> 2);
    int r1 = r0 + 8;

#pragma unroll
    for (int nt = 0; nt < 8; nt++) {
        int col = nt * 8 + 2 * q;
        if (r0 < NN)
            *(float2*)(g_h1 + (size_t)r0 * 64 + col) = make_float2(acc[nt][0], acc[nt][1]);
        if (r1 < NN)
            *(float2*)(g_h1 + (size_t)r1 * 64 + col) = make_float2(acc[nt][2], acc[nt][3]);
    }

#pragma unroll
    for (int h = 0; h < 8; h++) {
        float as0 = sA[h * 8 + 2 * q], as1v = sA[h * 8 + 2 * q + 1];
        float ad0 = sA[64 + h * 8 + 2 * q], ad1v = sA[64 + h * 8 + 2 * q + 1];
        float s0 = acc[h][0] * as0 + acc[h][1] * as1v;
        float d0 = acc[h][0] * ad0 + acc[h][1] * ad1v;
        float s1 = acc[h][2] * as0 + acc[h][3] * as1v;
        float d1 = acc[h][2] * ad0 + acc[h][3] * ad1v;
#pragma unroll
        for (int o = 1; o <= 2; o <<= 1) {
            s0 += __shfl_xor_sync(FULL, s0, o);
            d0 += __shfl_xor_sync(FULL, d0, o);
            s1 += __shfl_xor_sync(FULL, s1, o);
            d1 += __shfl_xor_sync(FULL, d1, o);
        }
        if (q == 0) {
            if (r0 < NN) { g_as1[r0 * 8 + h] = s0; g_ad1[r0 * 8 + h] = d0; }
            if (r1 < NN) { g_as1[r1 * 8 + h] = s1; g_ad1[r1 * 8 + h] = d1; }
        }
    }
}

// ---------------- scans ----------------
__global__ void s1_scan() {
    __shared__ int sd[SCAN_B];
    int i = blockIdx.x * SCAN_B + threadIdx.x;
    int v = (i < NN) ? g_deg[i] : 0;
    sd[threadIdx.x] = v;
    __syncthreads();
    for (int ofs = 1; ofs < SCAN_B; ofs <<= 1) {
        int t = (threadIdx.x >= ofs) ? sd[threadIdx.x - ofs] : 0;
        __syncthreads();
        sd[threadIdx.x] += t;
        __syncthreads();
    }
    if (i < NN) g_off[i] = sd[threadIdx.x] - v;
    if (threadIdx.x == SCAN_B - 1) g_bsum[blockIdx.x] = sd[threadIdx.x];
}

__global__ void s3_apply() {
    __shared__ int sbase;
    int b = blockIdx.x;
    if (threadIdx.x < 32) {
        int p = 0;
        for (int i = threadIdx.x; i < b; i += 32) p += g_bsum[i];
#pragma unroll
        for (int o = 16; o; o >>= 1) p += __shfl_xor_sync(FULL, p, o);
        if (threadIdx.x == 0) sbase = p;
    }
    __syncthreads();
    int i = b * SCAN_B + threadIdx.x;
    if (i < NN) {
        int o = g_off[i] + sbase;
        g_off[i] = o;
        if (i == NN - 1) g_off[NN] = o + g_deg[i];   // sentinel
        g_deg[i] = 0;                                 // ready for next replay
    }
}

// ---------------- scatter: atomic-free (uses precomputed uint16 ranks) ----------------
__global__ void k_scatter(const int* __restrict__ src, const int* __restrict__ dst) {
    int t = blockIdx.x * blockDim.x + threadIdx.x;
    if (t >= EE / 4) return;
    int4 s4 = ((const int4*)src)[t];
    int4 d4 = ((const int4*)dst)[t];
    ushort4 r4 = ((const ushort4*)g_rank16)[t];
    g_csr[g_off[d4.x] + r4.x] = s4.x;
    g_csr[g_off[d4.y] + r4.y] = s4.y;
    g_csr[g_off[d4.z] + r4.z] = s4.z;
    g_csr[g_off[d4.w] + r4.w] = s4.w;
}

// ---------------- G1: warp-per-dst gather, 8 edges in flight ----------------
__global__ void __launch_bounds__(256) g1_gather(const float* __restrict__ b1) {
    int warp = (blockIdx.x * 256 + threadIdx.x) >> 5;
    int lane = threadIdx.x & 31;
    if (warp >= NN) return;
    int n = warp;
    int off = g_off[n];
    int deg = g_off[n + 1] - off;
    int h8 = lane & 7;
    int h4 = lane >> 2;
    float adf = g_ad1[n * 8 + h8];

    float2 acc = make_float2(0.0f, 0.0f);
    float den = 0.0f;

    int sreg = (lane < deg) ? g_csr[off + lane] : 0;

    for (int base = 0; base < deg; base += 32) {
        int sreg_n = 0;
        if (base + 32 < deg) {
            int nl = base + 32 + lane;
            sreg_n = (nl < deg) ? g_csr[off + nl] : 0;
        }
        int cnt = min(32, deg - base);

        int sl0 = __shfl_sync(FULL, sreg, lane >> 3);
        float as = g_as1[sl0 * 8 + h8];

        for (int g = 0; g < cnt; g += 8) {
            bool hasB = (g + 4 < cnt);
            float asB = 0.0f;
            if (hasB) {
                int slB = __shfl_sync(FULL, sreg, g + 4 + (lane >> 3));
                asB = g_as1[slB * 8 + h8];
            }
            float as_nx = 0.0f;
            if (g + 8 < cnt) {
                int slN = __shfl_sync(FULL, sreg, g + 8 + (lane >> 3));
                as_nx = g_as1[slN * 8 + h8];
            }

            float eA = as + adf;
            eA = (eA >= 0.0f) ? eA : NEG_SLOPE * eA;
            float pA = __expf(eA);
            if (base + g + (lane >> 3) >= deg) pA = 0.0f;

            float pB = 0.0f;
            if (hasB) {
                float eB = asB + adf;
                eB = (eB >= 0.0f) ? eB : NEG_SLOPE * eB;
                pB = __expf(eB);
                if (base + g + 4 + (lane >> 3) >= deg) pB = 0.0f;
            }

            float2 v[8];
            float pj[8];
#pragma unroll
            for (int j = 0; j < 4; j++) {
                int s = __shfl_sync(FULL, sreg, g + j);
                pj[j] = __shfl_sync(FULL, pA, j * 8 + h4);
                v[j] = *(const float2*)(g_h1 + (size_t)s * 64 + 2 * lane);
            }
#pragma unroll
            for (int j = 0; j < 4; j++) {
                int s = __shfl_sync(FULL, sreg, g + 4 + j);
                pj[4 + j] = __shfl_sync(FULL, pB, j * 8 + h4);
                v[4 + j] = *(const float2*)(g_h1 + (size_t)s * 64 + 2 * lane);
            }
#pragma unroll
            for (int j = 0; j < 8; j++) {
                acc.x += pj[j] * v[j].x;
                acc.y += pj[j] * v[j].y;
                den += pj[j];
            }
            as = as_nx;
        }
        sreg = sreg_n;
    }

    float inv = (den > 0.0f) ? (1.0f / den) : 0.0f;
    float r0 = acc.x * inv + b1[2 * lane];
    float r1 = acc.y * inv + b1[2 * lane + 1];
    r0 = (r0 > 0.0f) ? r0 : (__expf(r0) - 1.0f);
    r1 = (r1 > 0.0f) ? r1 : (__expf(r1) - 1.0f);
    *(__half2*)(g_out1h + (size_t)n * 64 + 2 * lane) = __floats2half2_rn(r0, r1);
}

// ---------------- K5: tensor-core GEMM2 (+layer2 attention logits), fp16 input ----------------
__global__ void __launch_bounds__(256) k5_gemm2(
    const float* __restrict__ W2, const float* __restrict__ a2s,
    const float* __restrict__ a2d)
{
    __shared__ __half xs[128 * 72];
    __shared__ __half ws[64 * 24];
    __shared__ float sA[32];

    int tid = threadIdx.x;
    int wid = tid >> 5, lane = tid & 31;
    int rowBase = blockIdx.x * 128;
    if (tid < 32) sA[tid] = (tid < 16) ? a2s[tid] : a2d[tid - 16];

    // raw copy fp16 rows -> xs (no conversion): 128 rows x 128B = 1024 int4
#pragma unroll
    for (int i = 0; i < 4; i++) {
        int idx = tid + i * 256;          // 1024 int4 total
        int r = idx >> 3;                 // 8 int4 per row
        int c8 = (idx & 7) * 8;           // half offset within row
        int grow = rowBase + r;
        int4 v = make_int4(0, 0, 0, 0);
        if (grow < NN)
            v = *(const int4*)(g_out1h + (size_t)grow * 64 + c8);
        *(int4*)(&xs[r * 72 + c8]) = v;
    }
    if (tid < 256) {
        int r = tid >> 2;
        int k4 = (tid & 3) * 4;
        float4 v = __ldg((const float4*)(W2 + (size_t)r * 16 + k4));
        *(__half2*)(&ws[r * 24 + k4])     = __floats2half2_rn(v.x, v.y);
        *(__half2*)(&ws[r * 24 + k4 + 2]) = __floats2half2_rn(v.z, v.w);
    }
    __syncthreads();

    float acc[2][4];
#pragma unroll
    for (int nt = 0; nt < 2; nt++)
#pragma unroll
        for (int c = 0; c < 4; c++) acc[nt][c] = 0.0f;

#pragma unroll
    for (int kcl = 0; kcl < 4; kcl++) {
        unsigned a0, a1, a2, a3;
        unsigned aaddr = su32(xs) +
            ((wid * 16 + (lane & 15)) * 72 + kcl * 16 + (lane >> 4) * 8) * 2;
        asm volatile(
            "ldmatrix.sync.aligned.m8n8.x4.shared.b16 {%0,%1,%2,%3}, [%4];"
            : "=r"(a0), "=r"(a1), "=r"(a2), "=r"(a3) : "r"(aaddr));
#pragma unroll
        for (int nt = 0; nt < 2; nt++) {
            unsigned b0, b1;
            unsigned baddr = su32(ws) +
                ((kcl * 16 + (lane & 15)) * 24 + nt * 8) * 2;
            asm volatile(
                "ldmatrix.sync.aligned.m8n8.x2.trans.shared.b16 {%0,%1}, [%2];"
                : "=r"(b0), "=r"(b1) : "r"(baddr));
            asm volatile(
                "mma.sync.aligned.m16n8k16.row.col.f32.f16.f16.f32 "
                "{%0,%1,%2,%3}, {%4,%5,%6,%7}, {%8,%9}, {%0,%1,%2,%3};"
                : "+f"(acc[nt][0]), "+f"(acc[nt][1]),
                  "+f"(acc[nt][2]), "+f"(acc[nt][3])
                : "r"(a0), "r"(a1), "r"(a2), "r"(a3), "r"(b0), "r"(b1));
        }
    }

    int q = lane & 3;
    int r0 = rowBase + wid * 16 + (lane >> 2);
    int r1 = r0 + 8;

#pragma unroll
    for (int nt = 0; nt < 2; nt++) {
        int col = nt * 8 + 2 * q;
        if (r0 < NN)
            *(float2*)(g_g2 + (size_t)r0 * 16 + col) = make_float2(acc[nt][0], acc[nt][1]);
        if (r1 < NN)
            *(float2*)(g_g2 + (size_t)r1 * 16 + col) = make_float2(acc[nt][2], acc[nt][3]);
    }

    float s0 = 0.0f, d0 = 0.0f, s1 = 0.0f, d1 = 0.0f;
#pragma unroll
    for (int nt = 0; nt < 2; nt++) {
        int c0 = nt * 8 + 2 * q, c1 = c0 + 1;
        s0 += acc[nt][0] * sA[c0] + acc[nt][1] * sA[c1];
        d0 += acc[nt][0] * sA[16 + c0] + acc[nt][1] * sA[16 + c1];
        s1 += acc[nt][2] * sA[c0] + acc[nt][3] * sA[c1];
        d1 += acc[nt][2] * sA[16 + c0] + acc[nt][3] * sA[16 + c1];
    }
#pragma unroll
    for (int o = 1; o <= 2; o <<= 1) {
        s0 += __shfl_xor_sync(FULL, s0, o);
        d0 += __shfl_xor_sync(FULL, d0, o);
        s1 += __shfl_xor_sync(FULL, s1, o);
        d1 += __shfl_xor_sync(FULL, d1, o);
    }
    if (q == 0) {
        if (r0 < NN) { g_as2[r0] = s0; g_ad2[r0] = d0; }
        if (r1 < NN) { g_as2[r1] = s1; g_ad2[r1] = d1; }
    }
}

// ---------------- G2: warp-per-dst gather, 4 edges in flight ----------------
__global__ void __launch_bounds__(256) g2_gather(const float* __restrict__ b2,
                                                 float* __restrict__ out) {
    int warp = (blockIdx.x * 256 + threadIdx.x) >> 5;
    int lane = threadIdx.x & 31;
    if (warp >= NN) return;
    int n = warp;
    int off = g_off[n];
    int deg = g_off[n + 1] - off;
    int half = lane >> 4;
    int d16 = lane & 15;
    float ad = g_ad2[n];

    float acc = 0.0f, den = 0.0f;

    int sreg = (lane < deg) ? g_csr[off + lane] : 0;
    float as = g_as2[sreg];

    for (int base = 0; base < deg; base += 32) {
        int sreg_n = 0;
        float as_n = 0.0f;
        if (base + 32 < deg) {
            int nl = base + 32 + lane;
            sreg_n = (nl < deg) ? g_csr[off + nl] : 0;
            as_n = g_as2[sreg_n];
        }

        float e = as + ad;
        e = (e >= 0.0f) ? e : NEG_SLOPE * e;
        float p = __expf(e);
        if (base + lane >= deg) p = 0.0f;
        int cnt = min(32, deg - base);

        int g = 0;
        for (; g + 4 <= cnt; g += 4) {
            int sa = __shfl_sync(FULL, sreg, g + half);
            float pa = __shfl_sync(FULL, p, g + half);
            int sb = __shfl_sync(FULL, sreg, g + 2 + half);
            float pb = __shfl_sync(FULL, p, g + 2 + half);
            float va = g_g2[(size_t)sa * 16 + d16];
            float vb = g_g2[(size_t)sb * 16 + d16];
            acc += pa * va;
            den += pa;
            acc += pb * vb;
            den += pb;
        }
        for (; g < cnt; g += 2) {
            int s = __shfl_sync(FULL, sreg, g + half);
            float pj = __shfl_sync(FULL, p, g + half);
            float v = g_g2[(size_t)s * 16 + d16];
            acc += pj * v;
            den += pj;
        }
        sreg = sreg_n;
        as = as_n;
    }

    acc += __shfl_xor_sync(FULL, acc, 16);
    den += __shfl_xor_sync(FULL, den, 16);

    float z = ((den > 0.0f) ? (acc / den) : 0.0f) + b2[d16];

    float m = z;
#pragma unroll
    for (int ofs = 1; ofs < 16; ofs <<= 1)
        m = fmaxf(m, __shfl_xor_sync(FULL, m, ofs));
    float sum = __expf(z - m);
#pragma unroll
    for (int ofs = 1; ofs < 16; ofs <<= 1)
        sum += __shfl_xor_sync(FULL, sum, ofs);
    float lse = m + logf(sum);

    if (lane < 16) out[(size_t)n * 16 + d16] = z - lse;
}

// ---------------- launcher ----------------
extern "C" void kernel_launch(void* const* d_in, const int* in_sizes, int n_in,
                              void* d_out, int out_size) {
    const float* x   = (const float*)d_in[0];
    const int*   ei  = (const int*)d_in[1];
    const float* W1  = (const float*)d_in[2];
    const float* a1s = (const float*)d_in[3];
    const float* a1d = (const float*)d_in[4];
    const float* b1  = (const float*)d_in[5];
    const float* W2  = (const float*)d_in[6];
    const float* a2s = (const float*)d_in[7];
    const float* a2d = (const float*)d_in[8];
    const float* b2  = (const float*)d_in[9];
    float* out = (float*)d_out;

    const int* src = ei;
    const int* dst = ei + EE;

    const int TB = 256;
    kA_gemm1_hist<<<TC_BLOCKS + HIST_BLOCKS, TB>>>(x, W1, a1s, a1d, dst);
    s1_scan<<<NBLK, SCAN_B>>>();
    s3_apply<<<NBLK, SCAN_B>>>();
    k_scatter<<<(EE / 4 + TB - 1) / TB, TB>>>(src, dst);
    g1_gather<<<(NN * 32 + TB - 1) / TB, TB>>>(b1);
    k5_gemm2<<<TC_BLOCKS, TB>>>(W2, a2s, a2d);
    g2_gather<<<(NN * 32 + TB - 1) / TB, TB>>>(b2, out);
}